// round 3
// baseline (speedup 1.0000x reference)
#include <cuda_runtime.h>

#define NNODES 50000
#define NREL   8
#define D      128
#define NSEG   (NREL * NNODES)      // 400000
#define MAXE   1700000
#define KTOT   (NREL * D + D)       // 1152

// -------- scratch (device globals; no allocation allowed) --------
__device__ int   g_deg[NSEG];
__device__ int   g_off[NSEG + 1];
__device__ int   g_cur[NSEG];
__device__ int   g_bsum[512];
__device__ int   g_sorted[MAXE];
__device__ int   g_st_ei;            // words per element of edge_index (1=int32, 2=int64)
__device__ int   g_st_et;            // words per element of edge_type
__device__ float g_agg[(size_t)NREL * NNODES * D];   // [r][node][d]

// -------- dtype detection (device-side, graph-capturable) --------
__global__ void k_detect(const int* __restrict__ ei_w, const int* __restrict__ et_w) {
    if (threadIdx.x == 0) {
        bool e64 = true, t64 = true;
        #pragma unroll
        for (int j = 1; j < 64; j += 2) {
            e64 = e64 && (ei_w[j] == 0);
            t64 = t64 && (et_w[j] == 0);
        }
        g_st_ei = e64 ? 2 : 1;
        g_st_et = t64 ? 2 : 1;
    }
}

__global__ void k_zero_deg() {
    int i = blockIdx.x * blockDim.x + threadIdx.x;
    if (i < NSEG) g_deg[i] = 0;
}

__global__ void k_hist(const int* __restrict__ ei_w, const int* __restrict__ et_w, int E) {
    int i = blockIdx.x * blockDim.x + threadIdx.x;
    if (i < E) {
        int st = g_st_ei, stt = g_st_et;
        int s = ei_w[(size_t)i * st];
        int t = et_w[(size_t)i * stt];
        int key = t * NNODES + s;
        if ((unsigned)key < NSEG) atomicAdd(&g_deg[key], 1);
    }
}

__global__ void k_scan1(int n) {
    __shared__ int sh[1024];
    int tid = threadIdx.x;
    int i = blockIdx.x * 1024 + tid;
    int v = (i < n) ? g_deg[i] : 0;
    sh[tid] = v;
    __syncthreads();
    #pragma unroll
    for (int off = 1; off < 1024; off <<= 1) {
        int t = (tid >= off) ? sh[tid - off] : 0;
        __syncthreads();
        sh[tid] += t;
        __syncthreads();
    }
    if (i < n) g_off[i] = sh[tid] - v;
    if (tid == 1023) g_bsum[blockIdx.x] = sh[1023];
}

__global__ void k_scan2(int nb) {
    __shared__ int sh[512];
    int tid = threadIdx.x;
    int v = (tid < nb) ? g_bsum[tid] : 0;
    sh[tid] = v;
    __syncthreads();
    #pragma unroll
    for (int off = 1; off < 512; off <<= 1) {
        int t = (tid >= off) ? sh[tid - off] : 0;
        __syncthreads();
        sh[tid] += t;
        __syncthreads();
    }
    if (tid < nb) g_bsum[tid] = sh[tid] - v;
}

__global__ void k_scan3(int n, int E) {
    int i = blockIdx.x * blockDim.x + threadIdx.x;
    if (i < n) {
        int o = g_off[i] + g_bsum[i >> 10];
        g_off[i] = o;
        g_cur[i] = o;
    }
    if (i == 0) g_off[n] = E;
}

__global__ void k_scatter(const int* __restrict__ ei_w, const int* __restrict__ et_w, int E) {
    int i = blockIdx.x * blockDim.x + threadIdx.x;
    if (i < E) {
        int st = g_st_ei, stt = g_st_et;
        int s = ei_w[(size_t)i * st];
        int d = ei_w[((size_t)E + i) * st];
        int t = et_w[(size_t)i * stt];
        int key = t * NNODES + s;
        if ((unsigned)key < NSEG) {
            int pos = atomicAdd(&g_cur[key], 1);
            if ((unsigned)pos < MAXE) g_sorted[pos] = d;
        }
    }
}

// -------- gather + mean: warp per (rel,node) segment --------
__global__ void k_gather(const float* __restrict__ x) {
    int wid  = (blockIdx.x * blockDim.x + threadIdx.x) >> 5;
    int lane = threadIdx.x & 31;
    if (wid >= NSEG) return;
    int s = g_off[wid];
    int e = g_off[wid + 1];
    float4 acc = make_float4(0.f, 0.f, 0.f, 0.f);
    for (int j = s; j < e; j++) {
        int d = g_sorted[j];
        const float4* row = (const float4*)(x + (size_t)d * D);
        float4 v = __ldg(row + lane);
        acc.x += v.x; acc.y += v.y; acc.z += v.z; acc.w += v.w;
    }
    float inv = (e > s) ? 1.0f / (float)(e - s) : 0.0f;
    acc.x *= inv; acc.y *= inv; acc.z *= inv; acc.w *= inv;
    ((float4*)(g_agg + (size_t)wid * D))[lane] = acc;
}

// -------- tf32 GEMM: out = [agg_0..agg_7, x] @ [W_0..W_7, root]^T + bias --------
__device__ __forceinline__ float tf32r(float v) {
    unsigned int u;
    asm("cvt.rna.tf32.f32 %0, %1;" : "=r"(u) : "f"(v));
    return __uint_as_float(u);
}

__device__ __forceinline__ void mma_tf32(float* c,
                                         unsigned a0, unsigned a1, unsigned a2, unsigned a3,
                                         unsigned b0, unsigned b1) {
    asm volatile(
        "mma.sync.aligned.m16n8k8.row.col.f32.tf32.tf32.f32 "
        "{%0,%1,%2,%3},{%4,%5,%6,%7},{%8,%9},{%0,%1,%2,%3};"
        : "+f"(c[0]), "+f"(c[1]), "+f"(c[2]), "+f"(c[3])
        : "r"(a0), "r"(a1), "r"(a2), "r"(a3), "r"(b0), "r"(b1));
}

__global__ void __launch_bounds__(128)
k_gemm(const float* __restrict__ x, const float* __restrict__ W,
       const float* __restrict__ root, const float* __restrict__ bias,
       float* __restrict__ out, int n) {
    __shared__ float As[32][65];    // [k][row]  (64 rows)
    __shared__ float Bs[32][129];   // [k][col]  (128 cols)

    int tid  = threadIdx.x;
    int lane = tid & 31;
    int warp = tid >> 5;
    int rowBase = blockIdx.x * 64;
    int gpr = lane >> 2;
    int tg  = lane & 3;
    int warpRow = warp * 16;

    float acc[16][4];
    #pragma unroll
    for (int t = 0; t < 16; t++)
        #pragma unroll
        for (int q = 0; q < 4; q++) acc[t][q] = 0.f;

    #pragma unroll 1
    for (int kt = 0; kt < KTOT / 32; kt++) {
        int ko = kt * 32;
        int r  = ko >> 7;
        int d0 = ko & 127;
        const float* Ag = (r < 8) ? (g_agg + ((size_t)r * NNODES + rowBase) * D + d0)
                                  : (x + (size_t)rowBase * D + d0);
        const float* Bg = (r < 8) ? (W + (size_t)r * D * D + d0)
                                  : (root + d0);
        __syncthreads();
        #pragma unroll
        for (int i = 0; i < 16; i++) {
            int linear = i * 128 + tid;
            int row = linear >> 5, c = linear & 31;
            float v = (rowBase + row < n) ? __ldg(Ag + (size_t)row * D + c) : 0.f;
            As[c][row] = tf32r(v);
        }
        #pragma unroll
        for (int i = 0; i < 32; i++) {
            int linear = i * 128 + tid;
            int o = linear >> 5, c = linear & 31;
            Bs[c][o] = tf32r(__ldg(Bg + (size_t)o * D + c));
        }
        __syncthreads();
        #pragma unroll
        for (int kk = 0; kk < 4; kk++) {
            int kb = kk * 8;
            unsigned a0 = __float_as_uint(As[kb + tg    ][warpRow + gpr    ]);
            unsigned a1 = __float_as_uint(As[kb + tg    ][warpRow + gpr + 8]);
            unsigned a2 = __float_as_uint(As[kb + tg + 4][warpRow + gpr    ]);
            unsigned a3 = __float_as_uint(As[kb + tg + 4][warpRow + gpr + 8]);
            #pragma unroll
            for (int t = 0; t < 16; t++) {
                unsigned b0 = __float_as_uint(Bs[kb + tg    ][t * 8 + gpr]);
                unsigned b1 = __float_as_uint(Bs[kb + tg + 4][t * 8 + gpr]);
                mma_tf32(acc[t], a0, a1, a2, a3, b0, b1);
            }
        }
    }

    #pragma unroll
    for (int t = 0; t < 16; t++) {
        int col = t * 8 + tg * 2;
        float bv0 = bias[col], bv1 = bias[col + 1];
        int row0 = rowBase + warpRow + gpr;
        int row1 = row0 + 8;
        if (row0 < n) {
            float2 v = make_float2(acc[t][0] + bv0, acc[t][1] + bv1);
            *(float2*)(out + (size_t)row0 * D + col) = v;
        }
        if (row1 < n) {
            float2 v = make_float2(acc[t][2] + bv0, acc[t][3] + bv1);
            *(float2*)(out + (size_t)row1 * D + col) = v;
        }
    }
}

extern "C" void kernel_launch(void* const* d_in, const int* in_sizes, int n_in,
                              void* d_out, int out_size) {
    const float* x    = (const float*)d_in[0];
    const int*   ei_w = (const int*)d_in[1];     // raw 32-bit word view
    const int*   et_w = (const int*)d_in[2];
    const float* W    = (const float*)d_in[3];
    const float* root = (const float*)d_in[4];
    const float* bias = (const float*)d_in[5];
    float*       out  = (float*)d_out;

    int E = in_sizes[1] / 2;      // elements, dtype-independent
    int n = in_sizes[0] / D;

    int nb = (NSEG + 1023) / 1024;

    k_detect <<<1, 32>>>(ei_w, et_w);
    k_zero_deg<<<(NSEG + 255) / 256, 256>>>();
    k_hist   <<<(E + 255) / 256, 256>>>(ei_w, et_w, E);
    k_scan1  <<<nb, 1024>>>(NSEG);
    k_scan2  <<<1, 512>>>(nb);
    k_scan3  <<<(NSEG + 255) / 256, 256>>>(NSEG, E);
    k_scatter<<<(E + 255) / 256, 256>>>(ei_w, et_w, E);
    k_gather <<<NSEG / 8, 256>>>(x);
    k_gemm   <<<(n + 63) / 64, 128>>>(x, W, root, bias, out, n);
}

// round 4
// speedup vs baseline: 2.1556x; 2.1556x over previous
#include <cuda_runtime.h>
#include <cuda_fp16.h>

#define NNODES 50000
#define NREL   8
#define D      128
#define NSEG   (NREL * NNODES)      // 400000
#define MAXE   1700000
#define ROWS   64                   // output rows per block
#define NTHR   128

// -------- scratch (device globals; no allocation allowed) --------
__device__ int    g_deg[NSEG];
__device__ int    g_off[NSEG + 1];
__device__ int    g_cur[NSEG];
__device__ int    g_bsum[512];
__device__ int    g_sorted[MAXE];
__device__ int    g_st_ei;           // words/elem of edge_index (1=int32, 2=int64)
__device__ int    g_st_et;
__device__ __half g_wh[(NREL + 1) * D * D];   // fp16 [W_0..W_7, root], [out][in]

// -------- dtype detection (device-side, graph-capturable) --------
__global__ void k_detect(const int* __restrict__ ei_w, const int* __restrict__ et_w) {
    if (threadIdx.x == 0) {
        bool e64 = true, t64 = true;
        #pragma unroll
        for (int j = 1; j < 64; j += 2) {
            e64 = e64 && (ei_w[j] == 0);
            t64 = t64 && (et_w[j] == 0);
        }
        g_st_ei = e64 ? 2 : 1;
        g_st_et = t64 ? 2 : 1;
    }
}

__global__ void k_cvtw(const float* __restrict__ W, const float* __restrict__ root) {
    int i = blockIdx.x * blockDim.x + threadIdx.x;
    const int nw = NREL * D * D;
    if (i < nw)               g_wh[i] = __float2half(W[i]);
    else if (i < nw + D * D)  g_wh[i] = __float2half(root[i - nw]);
}

__global__ void k_zero_deg() {
    int i = blockIdx.x * blockDim.x + threadIdx.x;
    if (i < NSEG) g_deg[i] = 0;
}

__global__ void k_hist(const int* __restrict__ ei_w, const int* __restrict__ et_w, int E) {
    int i = blockIdx.x * blockDim.x + threadIdx.x;
    if (i < E) {
        int st = g_st_ei, stt = g_st_et;
        int s = ei_w[(size_t)i * st];
        int t = et_w[(size_t)i * stt];
        int key = t * NNODES + s;
        if ((unsigned)key < NSEG) atomicAdd(&g_deg[key], 1);
    }
}

__global__ void k_scan1(int n) {
    __shared__ int sh[1024];
    int tid = threadIdx.x;
    int i = blockIdx.x * 1024 + tid;
    int v = (i < n) ? g_deg[i] : 0;
    sh[tid] = v;
    __syncthreads();
    #pragma unroll
    for (int off = 1; off < 1024; off <<= 1) {
        int t = (tid >= off) ? sh[tid - off] : 0;
        __syncthreads();
        sh[tid] += t;
        __syncthreads();
    }
    if (i < n) g_off[i] = sh[tid] - v;
    if (tid == 1023) g_bsum[blockIdx.x] = sh[1023];
}

__global__ void k_scan2(int nb) {
    __shared__ int sh[512];
    int tid = threadIdx.x;
    int v = (tid < nb) ? g_bsum[tid] : 0;
    sh[tid] = v;
    __syncthreads();
    #pragma unroll
    for (int off = 1; off < 512; off <<= 1) {
        int t = (tid >= off) ? sh[tid - off] : 0;
        __syncthreads();
        sh[tid] += t;
        __syncthreads();
    }
    if (tid < nb) g_bsum[tid] = sh[tid] - v;
}

__global__ void k_scan3(int n, int E) {
    int i = blockIdx.x * blockDim.x + threadIdx.x;
    if (i < n) {
        int o = g_off[i] + g_bsum[i >> 10];
        g_off[i] = o;
        g_cur[i] = o;
    }
    if (i == 0) g_off[n] = E;
}

__global__ void k_scatter(const int* __restrict__ ei_w, const int* __restrict__ et_w, int E) {
    int i = blockIdx.x * blockDim.x + threadIdx.x;
    if (i < E) {
        int st = g_st_ei, stt = g_st_et;
        int s = ei_w[(size_t)i * st];
        int d = ei_w[((size_t)E + i) * st];
        int t = et_w[(size_t)i * stt];
        int key = t * NNODES + s;
        if ((unsigned)key < NSEG) {
            int pos = atomicAdd(&g_cur[key], 1);
            if ((unsigned)pos < MAXE) g_sorted[pos] = d;
        }
    }
}

// -------- fused gather-mean + fp16 MMA GEMM --------
__device__ __forceinline__ void mma_f16(float* c,
                                        unsigned a0, unsigned a1, unsigned a2, unsigned a3,
                                        unsigned b0, unsigned b1) {
    asm volatile(
        "mma.sync.aligned.m16n8k16.row.col.f32.f16.f16.f32 "
        "{%0,%1,%2,%3},{%4,%5,%6,%7},{%8,%9},{%0,%1,%2,%3};"
        : "+f"(c[0]), "+f"(c[1]), "+f"(c[2]), "+f"(c[3])
        : "r"(a0), "r"(a1), "r"(a2), "r"(a3), "r"(b0), "r"(b1));
}

__global__ void __launch_bounds__(NTHR)
k_fused(const float* __restrict__ x, const float* __restrict__ bias,
        float* __restrict__ out, int n) {
    __shared__ __half As[ROWS][D + 8];   // [row][k]
    __shared__ __half Bs[D][D + 8];      // [ncol][k]

    int tid  = threadIdx.x;
    int lane = tid & 31;
    int warp = tid >> 5;
    int rowBase = blockIdx.x * ROWS;
    int gpr = lane >> 2;
    int tg  = lane & 3;
    int warpRow = warp * 16;

    float acc[16][4];
    #pragma unroll
    for (int t = 0; t < 16; t++)
        #pragma unroll
        for (int q = 0; q < 4; q++) acc[t][q] = 0.f;

    #pragma unroll 1
    for (int s = 0; s < NREL + 1; s++) {
        __syncthreads();   // previous MMA reads done before tiles overwritten

        // ---- stage B tile: W_s (or root) fp16, [out][in] ----
        const __half* Bg = g_wh + (size_t)s * D * D;
        #pragma unroll
        for (int i = 0; i < (D * D / 8) / NTHR; i++) {
            int idx = i * NTHR + tid;            // 8 halves per idx
            int o = idx >> 4, c = (idx & 15) * 8;
            *(uint4*)&Bs[o][c] = *(const uint4*)&Bg[o * D + c];
        }

        // ---- stage A tile: gather+mean (rels) or x (root slab) ----
        if (s < NREL) {
            for (int i = warp; i < ROWS; i += 4) {
                int node = rowBase + i;
                float4 a = make_float4(0.f, 0.f, 0.f, 0.f);
                if (node < n) {
                    int seg = s * NNODES + node;
                    int e0 = g_off[seg];
                    int e1 = g_off[seg + 1];
                    int j = e0;
                    // unroll-by-2 for MLP
                    for (; j + 1 < e1; j += 2) {
                        int d0 = __ldg(&g_sorted[j]);
                        int d1 = __ldg(&g_sorted[j + 1]);
                        float4 v0 = __ldg((const float4*)(x + (size_t)d0 * D) + lane);
                        float4 v1 = __ldg((const float4*)(x + (size_t)d1 * D) + lane);
                        a.x += v0.x + v1.x; a.y += v0.y + v1.y;
                        a.z += v0.z + v1.z; a.w += v0.w + v1.w;
                    }
                    if (j < e1) {
                        int d0 = __ldg(&g_sorted[j]);
                        float4 v0 = __ldg((const float4*)(x + (size_t)d0 * D) + lane);
                        a.x += v0.x; a.y += v0.y; a.z += v0.z; a.w += v0.w;
                    }
                    float inv = (e1 > e0) ? 1.0f / (float)(e1 - e0) : 0.0f;
                    a.x *= inv; a.y *= inv; a.z *= inv; a.w *= inv;
                }
                *(__half2*)&As[i][lane * 4]     = __floats2half2_rn(a.x, a.y);
                *(__half2*)&As[i][lane * 4 + 2] = __floats2half2_rn(a.z, a.w);
            }
        } else {
            for (int i = warp; i < ROWS; i += 4) {
                int node = rowBase + i;
                float4 a = make_float4(0.f, 0.f, 0.f, 0.f);
                if (node < n)
                    a = __ldg((const float4*)(x + (size_t)node * D) + lane);
                *(__half2*)&As[i][lane * 4]     = __floats2half2_rn(a.x, a.y);
                *(__half2*)&As[i][lane * 4 + 2] = __floats2half2_rn(a.z, a.w);
            }
        }
        __syncthreads();

        // ---- MMA over this K=128 slab: 8 ksteps of 16 ----
        #pragma unroll
        for (int kk = 0; kk < 8; kk++) {
            int kb = kk * 16;
            unsigned a0 = *(unsigned*)&As[warpRow + gpr    ][kb + tg * 2];
            unsigned a1 = *(unsigned*)&As[warpRow + gpr + 8][kb + tg * 2];
            unsigned a2 = *(unsigned*)&As[warpRow + gpr    ][kb + tg * 2 + 8];
            unsigned a3 = *(unsigned*)&As[warpRow + gpr + 8][kb + tg * 2 + 8];
            #pragma unroll
            for (int t = 0; t < 16; t++) {
                unsigned b0 = *(unsigned*)&Bs[t * 8 + gpr][kb + tg * 2];
                unsigned b1 = *(unsigned*)&Bs[t * 8 + gpr][kb + tg * 2 + 8];
                mma_f16(acc[t], a0, a1, a2, a3, b0, b1);
            }
        }
    }

    // ---- epilogue: + bias, store fp32 ----
    #pragma unroll
    for (int t = 0; t < 16; t++) {
        int col = t * 8 + tg * 2;
        float bv0 = bias[col], bv1 = bias[col + 1];
        int row0 = rowBase + warpRow + gpr;
        int row1 = row0 + 8;
        if (row0 < n) {
            float2 v = make_float2(acc[t][0] + bv0, acc[t][1] + bv1);
            *(float2*)(out + (size_t)row0 * D + col) = v;
        }
        if (row1 < n) {
            float2 v = make_float2(acc[t][2] + bv0, acc[t][3] + bv1);
            *(float2*)(out + (size_t)row1 * D + col) = v;
        }
    }
}

extern "C" void kernel_launch(void* const* d_in, const int* in_sizes, int n_in,
                              void* d_out, int out_size) {
    const float* x    = (const float*)d_in[0];
    const int*   ei_w = (const int*)d_in[1];
    const int*   et_w = (const int*)d_in[2];
    const float* W    = (const float*)d_in[3];
    const float* root = (const float*)d_in[4];
    const float* bias = (const float*)d_in[5];
    float*       out  = (float*)d_out;

    int E = in_sizes[1] / 2;
    int n = in_sizes[0] / D;
    int nb = (NSEG + 1023) / 1024;
    int nwh = (NREL + 1) * D * D;

    k_detect <<<1, 32>>>(ei_w, et_w);
    k_cvtw   <<<(nwh + 255) / 256, 256>>>(W, root);
    k_zero_deg<<<(NSEG + 255) / 256, 256>>>();
    k_hist   <<<(E + 255) / 256, 256>>>(ei_w, et_w, E);
    k_scan1  <<<nb, 1024>>>(NSEG);
    k_scan2  <<<1, 512>>>(nb);
    k_scan3  <<<(NSEG + 255) / 256, 256>>>(NSEG, E);
    k_scatter<<<(E + 255) / 256, 256>>>(ei_w, et_w, E);
    k_fused  <<<(n + ROWS - 1) / ROWS, NTHR>>>(x, bias, out, n);
}

// round 5
// speedup vs baseline: 3.0461x; 1.4131x over previous
#include <cuda_runtime.h>
#include <cuda_fp16.h>

#define NNODES 50000
#define NREL   8
#define D      128
#define NSEG   (NREL * NNODES)      // 400000
#define MAXE   1700000
#define ROWS   64                   // output rows per block
#define NTHR   256

// -------- scratch (device globals; no allocation allowed) --------
__device__ int    g_deg[NSEG];
__device__ int    g_off[NSEG + 1];
__device__ int    g_cur[NSEG];
__device__ int    g_bsum[512];
__device__ int    g_sorted[MAXE];
__device__ int    g_st_ei;           // words/elem of edge_index (1=int32, 2=int64)
__device__ int    g_st_et;
__device__ __half g_wh[(NREL + 1) * D * D];   // fp16 [W_0..W_7, root], [out][in]
__device__ __half g_xh[(size_t)NNODES * D];   // fp16 copy of x

// -------- dtype detection (device-side, graph-capturable) --------
__global__ void k_detect(const int* __restrict__ ei_w, const int* __restrict__ et_w) {
    if (threadIdx.x == 0) {
        bool e64 = true, t64 = true;
        #pragma unroll
        for (int j = 1; j < 64; j += 2) {
            e64 = e64 && (ei_w[j] == 0);
            t64 = t64 && (et_w[j] == 0);
        }
        g_st_ei = e64 ? 2 : 1;
        g_st_et = t64 ? 2 : 1;
    }
}

__global__ void k_cvtw(const float* __restrict__ W, const float* __restrict__ root) {
    int i = blockIdx.x * blockDim.x + threadIdx.x;
    const int nw = NREL * D * D;
    if (i < nw)               g_wh[i] = __float2half(W[i]);
    else if (i < nw + D * D)  g_wh[i] = __float2half(root[i - nw]);
}

__global__ void k_cvtx(const float* __restrict__ x, int n) {
    int i = blockIdx.x * blockDim.x + threadIdx.x;   // one float4 -> 4 halves
    int total = n * D / 4;
    if (i < total) {
        float4 v = __ldg((const float4*)x + i);
        __half2* o = (__half2*)(g_xh + (size_t)i * 4);
        o[0] = __floats2half2_rn(v.x, v.y);
        o[1] = __floats2half2_rn(v.z, v.w);
    }
}

__global__ void k_zero_deg() {
    int i = blockIdx.x * blockDim.x + threadIdx.x;
    if (i < NSEG) g_deg[i] = 0;
}

__global__ void k_hist(const int* __restrict__ ei_w, const int* __restrict__ et_w, int E) {
    int i = blockIdx.x * blockDim.x + threadIdx.x;
    if (i < E) {
        int st = g_st_ei, stt = g_st_et;
        int s = ei_w[(size_t)i * st];
        int t = et_w[(size_t)i * stt];
        int key = t * NNODES + s;
        if ((unsigned)key < NSEG) atomicAdd(&g_deg[key], 1);
    }
}

__global__ void k_scan1(int n) {
    __shared__ int sh[1024];
    int tid = threadIdx.x;
    int i = blockIdx.x * 1024 + tid;
    int v = (i < n) ? g_deg[i] : 0;
    sh[tid] = v;
    __syncthreads();
    #pragma unroll
    for (int off = 1; off < 1024; off <<= 1) {
        int t = (tid >= off) ? sh[tid - off] : 0;
        __syncthreads();
        sh[tid] += t;
        __syncthreads();
    }
    if (i < n) g_off[i] = sh[tid] - v;
    if (tid == 1023) g_bsum[blockIdx.x] = sh[1023];
}

__global__ void k_scan2(int nb) {
    __shared__ int sh[512];
    int tid = threadIdx.x;
    int v = (tid < nb) ? g_bsum[tid] : 0;
    sh[tid] = v;
    __syncthreads();
    #pragma unroll
    for (int off = 1; off < 512; off <<= 1) {
        int t = (tid >= off) ? sh[tid - off] : 0;
        __syncthreads();
        sh[tid] += t;
        __syncthreads();
    }
    if (tid < nb) g_bsum[tid] = sh[tid] - v;
}

__global__ void k_scan3(int n, int E) {
    int i = blockIdx.x * blockDim.x + threadIdx.x;
    if (i < n) {
        int o = g_off[i] + g_bsum[i >> 10];
        g_off[i] = o;
        g_cur[i] = o;
    }
    if (i == 0) g_off[n] = E;
}

__global__ void k_scatter(const int* __restrict__ ei_w, const int* __restrict__ et_w, int E) {
    int i = blockIdx.x * blockDim.x + threadIdx.x;
    if (i < E) {
        int st = g_st_ei, stt = g_st_et;
        int s = ei_w[(size_t)i * st];
        int d = ei_w[((size_t)E + i) * st];
        int t = et_w[(size_t)i * stt];
        int key = t * NNODES + s;
        if ((unsigned)key < NSEG) {
            int pos = atomicAdd(&g_cur[key], 1);
            if ((unsigned)pos < MAXE) g_sorted[pos] = d;
        }
    }
}

// -------- fused gather-mean + fp16 MMA GEMM --------
__device__ __forceinline__ void mma_f16(float* c,
                                        unsigned a0, unsigned a1, unsigned a2, unsigned a3,
                                        unsigned b0, unsigned b1) {
    asm volatile(
        "mma.sync.aligned.m16n8k16.row.col.f32.f16.f16.f32 "
        "{%0,%1,%2,%3},{%4,%5,%6,%7},{%8,%9},{%0,%1,%2,%3};"
        : "+f"(c[0]), "+f"(c[1]), "+f"(c[2]), "+f"(c[3])
        : "r"(a0), "r"(a1), "r"(a2), "r"(a3), "r"(b0), "r"(b1));
}

__device__ __forceinline__ void acc_h4(float4& a, uint2 u) {
    float2 f0 = __half22float2(*(__half2*)&u.x);
    float2 f1 = __half22float2(*(__half2*)&u.y);
    a.x += f0.x; a.y += f0.y; a.z += f1.x; a.w += f1.y;
}

__global__ void __launch_bounds__(NTHR)
k_fused(const float* __restrict__ bias, float* __restrict__ out, int n) {
    __shared__ __half As[ROWS][D + 8];   // [row][k]
    __shared__ __half Bs[D][D + 8];      // [ncol][k]

    int tid  = threadIdx.x;
    int lane = tid & 31;
    int warp = tid >> 5;
    int rowBase = blockIdx.x * ROWS;
    int gpr = lane >> 2;
    int tg  = lane & 3;
    int warpRow = (warp & 3) * 16;       // row strip within block
    int colBase = (warp >> 2) * 64;      // n-half handled by this warp

    float acc[8][4];
    #pragma unroll
    for (int t = 0; t < 8; t++)
        #pragma unroll
        for (int q = 0; q < 4; q++) acc[t][q] = 0.f;

    #pragma unroll 1
    for (int s = 0; s < NREL + 1; s++) {
        __syncthreads();   // previous MMA reads done before tiles overwritten

        // ---- stage B tile (all 256 threads): W_s fp16, [out][in] ----
        const __half* Bg = g_wh + (size_t)s * D * D;
        #pragma unroll
        for (int i = 0; i < (D * D / 8) / NTHR; i++) {
            int idx = i * NTHR + tid;            // 8 halves per idx
            int o = idx >> 4, c = (idx & 15) * 8;
            *(uint4*)&Bs[o][c] = *(const uint4*)&Bg[o * D + c];
        }

        // ---- stage A tile: gather+mean (rels) or x (root slab) ----
        if (s < NREL) {
            for (int i = warp; i < ROWS; i += 8) {
                int node = rowBase + i;
                float4 a = make_float4(0.f, 0.f, 0.f, 0.f);
                if (node < n) {
                    int seg = s * NNODES + node;
                    int e0 = g_off[seg];
                    int cnt = g_off[seg + 1] - e0;
                    for (int base = 0; base < cnt; base += 32) {
                        int m = min(32, cnt - base);
                        int idxv = (lane < m) ? __ldg(&g_sorted[e0 + base + lane]) : 0;
                        int j = 0;
                        for (; j + 3 < m; j += 4) {
                            int d0 = __shfl_sync(0xffffffffu, idxv, j);
                            int d1 = __shfl_sync(0xffffffffu, idxv, j + 1);
                            int d2 = __shfl_sync(0xffffffffu, idxv, j + 2);
                            int d3 = __shfl_sync(0xffffffffu, idxv, j + 3);
                            uint2 u0 = __ldg((const uint2*)(g_xh + (size_t)d0 * D) + lane);
                            uint2 u1 = __ldg((const uint2*)(g_xh + (size_t)d1 * D) + lane);
                            uint2 u2 = __ldg((const uint2*)(g_xh + (size_t)d2 * D) + lane);
                            uint2 u3 = __ldg((const uint2*)(g_xh + (size_t)d3 * D) + lane);
                            acc_h4(a, u0); acc_h4(a, u1); acc_h4(a, u2); acc_h4(a, u3);
                        }
                        for (; j < m; j++) {
                            int d0 = __shfl_sync(0xffffffffu, idxv, j);
                            uint2 u0 = __ldg((const uint2*)(g_xh + (size_t)d0 * D) + lane);
                            acc_h4(a, u0);
                        }
                    }
                    if (cnt > 0) {
                        float inv = 1.0f / (float)cnt;
                        a.x *= inv; a.y *= inv; a.z *= inv; a.w *= inv;
                    }
                }
                __half2* dst = (__half2*)&As[i][lane * 4];
                dst[0] = __floats2half2_rn(a.x, a.y);
                dst[1] = __floats2half2_rn(a.z, a.w);
            }
        } else {
            for (int i = warp; i < ROWS; i += 8) {
                int node = rowBase + i;
                uint2 u = make_uint2(0u, 0u);
                if (node < n)
                    u = __ldg((const uint2*)(g_xh + (size_t)node * D) + lane);
                *(uint2*)&As[i][lane * 4] = u;   // raw fp16 copy
            }
        }
        __syncthreads();

        // ---- MMA over this K=128 slab: 8 ksteps of 16, 64 cols per warp ----
        #pragma unroll
        for (int kk = 0; kk < 8; kk++) {
            int kb = kk * 16;
            unsigned a0 = *(unsigned*)&As[warpRow + gpr    ][kb + tg * 2];
            unsigned a1 = *(unsigned*)&As[warpRow + gpr + 8][kb + tg * 2];
            unsigned a2 = *(unsigned*)&As[warpRow + gpr    ][kb + tg * 2 + 8];
            unsigned a3 = *(unsigned*)&As[warpRow + gpr + 8][kb + tg * 2 + 8];
            #pragma unroll
            for (int t = 0; t < 8; t++) {
                unsigned b0 = *(unsigned*)&Bs[colBase + t * 8 + gpr][kb + tg * 2];
                unsigned b1 = *(unsigned*)&Bs[colBase + t * 8 + gpr][kb + tg * 2 + 8];
                mma_f16(acc[t], a0, a1, a2, a3, b0, b1);
            }
        }
    }

    // ---- epilogue: + bias, store fp32 ----
    #pragma unroll
    for (int t = 0; t < 8; t++) {
        int col = colBase + t * 8 + tg * 2;
        float bv0 = bias[col], bv1 = bias[col + 1];
        int row0 = rowBase + warpRow + gpr;
        int row1 = row0 + 8;
        if (row0 < n) {
            float2 v = make_float2(acc[t][0] + bv0, acc[t][1] + bv1);
            *(float2*)(out + (size_t)row0 * D + col) = v;
        }
        if (row1 < n) {
            float2 v = make_float2(acc[t][2] + bv0, acc[t][3] + bv1);
            *(float2*)(out + (size_t)row1 * D + col) = v;
        }
    }
}

extern "C" void kernel_launch(void* const* d_in, const int* in_sizes, int n_in,
                              void* d_out, int out_size) {
    const float* x    = (const float*)d_in[0];
    const int*   ei_w = (const int*)d_in[1];
    const int*   et_w = (const int*)d_in[2];
    const float* W    = (const float*)d_in[3];
    const float* root = (const float*)d_in[4];
    const float* bias = (const float*)d_in[5];
    float*       out  = (float*)d_out;

    int E = in_sizes[1] / 2;
    int n = in_sizes[0] / D;
    int nb = (NSEG + 1023) / 1024;
    int nwh = (NREL + 1) * D * D;
    int nx4 = n * D / 4;

    k_detect <<<1, 32>>>(ei_w, et_w);
    k_cvtw   <<<(nwh + 255) / 256, 256>>>(W, root);
    k_cvtx   <<<(nx4 + 255) / 256, 256>>>(x, n);
    k_zero_deg<<<(NSEG + 255) / 256, 256>>>();
    k_hist   <<<(E + 255) / 256, 256>>>(ei_w, et_w, E);
    k_scan1  <<<nb, 1024>>>(NSEG);
    k_scan2  <<<1, 512>>>(nb);
    k_scan3  <<<(NSEG + 255) / 256, 256>>>(NSEG, E);
    k_scatter<<<(E + 255) / 256, 256>>>(ei_w, et_w, E);
    k_fused  <<<(n + ROWS - 1) / ROWS, NTHR>>>(bias, out, n);
}

// round 6
// speedup vs baseline: 3.1804x; 1.0441x over previous
#include <cuda_runtime.h>
#include <cuda_fp16.h>

#define NNODES 50000
#define NREL   8
#define D      128
#define NSEG   (NREL * NNODES)      // 400000
#define MAXE   1700000
#define ROWS   128                  // output rows per block
#define NTHR   512

// -------- scratch (device globals; no allocation allowed) --------
__device__ int    g_deg[NSEG];
__device__ int    g_off[NSEG + 1];
__device__ int    g_cur[NSEG];
__device__ int    g_bsum[512];
__device__ int    g_sorted[MAXE];
__device__ int    g_st_ei;           // words/elem of edge_index (1=int32, 2=int64)
__device__ int    g_st_et;
__device__ __half g_wh[(NREL + 1) * D * D];   // fp16 [W_0..W_7, root], [out][in]
__device__ __half g_xh[(size_t)NNODES * D];   // fp16 copy of x

// -------- merged setup: detect dtype + cvt W/x to fp16 + zero deg --------
__global__ void k_prep(const float* __restrict__ W, const float* __restrict__ root,
                       const float* __restrict__ x, int n,
                       const int* __restrict__ ei_w, const int* __restrict__ et_w) {
    int i = blockIdx.x * blockDim.x + threadIdx.x;
    int stride = gridDim.x * blockDim.x;
    if (i == 0) {
        bool e64 = true, t64 = true;
        #pragma unroll
        for (int j = 1; j < 64; j += 2) {
            e64 = e64 && (ei_w[j] == 0);
            t64 = t64 && (et_w[j] == 0);
        }
        g_st_ei = e64 ? 2 : 1;
        g_st_et = t64 ? 2 : 1;
    }
    for (int j = i; j < NSEG; j += stride) g_deg[j] = 0;
    const int nw = NREL * D * D;
    for (int j = i; j < nw + D * D; j += stride)
        g_wh[j] = __float2half(j < nw ? W[j] : root[j - nw]);
    int nx4 = n * D / 4;
    for (int j = i; j < nx4; j += stride) {
        float4 v = __ldg((const float4*)x + j);
        __half2* o = (__half2*)(g_xh + (size_t)j * 4);
        o[0] = __floats2half2_rn(v.x, v.y);
        o[1] = __floats2half2_rn(v.z, v.w);
    }
}

__global__ void k_hist(const int* __restrict__ ei_w, const int* __restrict__ et_w, int E) {
    int i = blockIdx.x * blockDim.x + threadIdx.x;
    if (i < E) {
        int st = g_st_ei, stt = g_st_et;
        int s = ei_w[(size_t)i * st];
        int t = et_w[(size_t)i * stt];
        int key = t * NNODES + s;
        if ((unsigned)key < NSEG) atomicAdd(&g_deg[key], 1);
    }
}

__global__ void k_scan1(int n) {
    __shared__ int sh[1024];
    int tid = threadIdx.x;
    int i = blockIdx.x * 1024 + tid;
    int v = (i < n) ? g_deg[i] : 0;
    sh[tid] = v;
    __syncthreads();
    #pragma unroll
    for (int off = 1; off < 1024; off <<= 1) {
        int t = (tid >= off) ? sh[tid - off] : 0;
        __syncthreads();
        sh[tid] += t;
        __syncthreads();
    }
    if (i < n) g_off[i] = sh[tid] - v;
    if (tid == 1023) g_bsum[blockIdx.x] = sh[1023];
}

__global__ void k_scan2(int nb) {
    __shared__ int sh[512];
    int tid = threadIdx.x;
    int v = (tid < nb) ? g_bsum[tid] : 0;
    sh[tid] = v;
    __syncthreads();
    #pragma unroll
    for (int off = 1; off < 512; off <<= 1) {
        int t = (tid >= off) ? sh[tid - off] : 0;
        __syncthreads();
        sh[tid] += t;
        __syncthreads();
    }
    if (tid < nb) g_bsum[tid] = sh[tid] - v;
}

__global__ void k_scan3(int n, int E) {
    int i = blockIdx.x * blockDim.x + threadIdx.x;
    if (i < n) {
        int o = g_off[i] + g_bsum[i >> 10];
        g_off[i] = o;
        g_cur[i] = o;
    }
    if (i == 0) g_off[n] = E;
}

__global__ void k_scatter(const int* __restrict__ ei_w, const int* __restrict__ et_w, int E) {
    int i = blockIdx.x * blockDim.x + threadIdx.x;
    if (i < E) {
        int st = g_st_ei, stt = g_st_et;
        int s = ei_w[(size_t)i * st];
        int d = ei_w[((size_t)E + i) * st];
        int t = et_w[(size_t)i * stt];
        int key = t * NNODES + s;
        if ((unsigned)key < NSEG) {
            int pos = atomicAdd(&g_cur[key], 1);
            if ((unsigned)pos < MAXE) g_sorted[pos] = d;
        }
    }
}

// -------- fused gather-mean + fp16 MMA GEMM --------
__device__ __forceinline__ void mma_f16(float* c,
                                        unsigned a0, unsigned a1, unsigned a2, unsigned a3,
                                        unsigned b0, unsigned b1) {
    asm volatile(
        "mma.sync.aligned.m16n8k16.row.col.f32.f16.f16.f32 "
        "{%0,%1,%2,%3},{%4,%5,%6,%7},{%8,%9},{%0,%1,%2,%3};"
        : "+f"(c[0]), "+f"(c[1]), "+f"(c[2]), "+f"(c[3])
        : "r"(a0), "r"(a1), "r"(a2), "r"(a3), "r"(b0), "r"(b1));
}

__device__ __forceinline__ void acc_h8(float* a, uint4 u) {
    float2 f0 = __half22float2(*(__half2*)&u.x);
    float2 f1 = __half22float2(*(__half2*)&u.y);
    float2 f2 = __half22float2(*(__half2*)&u.z);
    float2 f3 = __half22float2(*(__half2*)&u.w);
    a[0] += f0.x; a[1] += f0.y; a[2] += f1.x; a[3] += f1.y;
    a[4] += f2.x; a[5] += f2.y; a[6] += f3.x; a[7] += f3.y;
}

__global__ void __launch_bounds__(NTHR)
k_fused(const float* __restrict__ bias, float* __restrict__ out, int n) {
    __shared__ __half As[ROWS][D + 8];   // [row][k]
    __shared__ __half Bs[D][D + 8];      // [ncol][k]

    int tid  = threadIdx.x;
    int lane = tid & 31;
    int warp = tid >> 5;                 // 0..15
    int hw   = lane >> 4;                // half-warp id (0/1)
    int hl   = lane & 15;                // lane within half-warp
    unsigned hmask = 0xFFFFu << (hw * 16);
    int rowBase = blockIdx.x * ROWS;
    int gpr = lane >> 2;
    int tg  = lane & 3;
    int rowStrip = (warp & 7) * 16;      // 8 row strips of 16
    int colBase  = (warp >> 3) * 64;     // 2 col halves

    float acc[8][4];
    #pragma unroll
    for (int t = 0; t < 8; t++)
        #pragma unroll
        for (int q = 0; q < 4; q++) acc[t][q] = 0.f;

    #pragma unroll 1
    for (int s = 0; s < NREL + 1; s++) {
        __syncthreads();   // previous MMA reads done before tiles overwritten

        // ---- stage B tile: W_s fp16, [out][in] ----
        const __half* Bg = g_wh + (size_t)s * D * D;
        #pragma unroll
        for (int i = 0; i < (D * D / 8) / NTHR; i++) {
            int idx = i * NTHR + tid;            // 8 halves per idx
            int o = idx >> 4, c = (idx & 15) * 8;
            *(uint4*)&Bs[o][c] = *(const uint4*)&Bg[o * D + c];
        }

        // ---- stage A tile: half-warp per row, gather+mean ----
        int rsub = warp * 2 + hw;                // 0..31
        if (s < NREL) {
            #pragma unroll 1
            for (int p = 0; p < ROWS / 32; p++) {
                int i = p * 32 + rsub;
                int node = rowBase + i;
                float a[8] = {0.f, 0.f, 0.f, 0.f, 0.f, 0.f, 0.f, 0.f};
                if (node < n) {
                    int seg = s * NNODES + node;
                    int e0 = g_off[seg];
                    int cnt = g_off[seg + 1] - e0;
                    for (int base = 0; base < cnt; base += 16) {
                        int m = min(16, cnt - base);
                        int idxv = (hl < m) ? __ldg(&g_sorted[e0 + base + hl]) : 0;
                        int j = 0;
                        for (; j + 3 < m; j += 4) {
                            int d0 = __shfl_sync(hmask, idxv, j,     16);
                            int d1 = __shfl_sync(hmask, idxv, j + 1, 16);
                            int d2 = __shfl_sync(hmask, idxv, j + 2, 16);
                            int d3 = __shfl_sync(hmask, idxv, j + 3, 16);
                            uint4 u0 = __ldg((const uint4*)(g_xh + (size_t)d0 * D) + hl);
                            uint4 u1 = __ldg((const uint4*)(g_xh + (size_t)d1 * D) + hl);
                            uint4 u2 = __ldg((const uint4*)(g_xh + (size_t)d2 * D) + hl);
                            uint4 u3 = __ldg((const uint4*)(g_xh + (size_t)d3 * D) + hl);
                            acc_h8(a, u0); acc_h8(a, u1); acc_h8(a, u2); acc_h8(a, u3);
                        }
                        for (; j < m; j++) {
                            int d0 = __shfl_sync(hmask, idxv, j, 16);
                            uint4 u0 = __ldg((const uint4*)(g_xh + (size_t)d0 * D) + hl);
                            acc_h8(a, u0);
                        }
                    }
                    if (cnt > 0) {
                        float inv = 1.0f / (float)cnt;
                        #pragma unroll
                        for (int q = 0; q < 8; q++) a[q] *= inv;
                    }
                }
                uint4 pk;
                ((__half2*)&pk)[0] = __floats2half2_rn(a[0], a[1]);
                ((__half2*)&pk)[1] = __floats2half2_rn(a[2], a[3]);
                ((__half2*)&pk)[2] = __floats2half2_rn(a[4], a[5]);
                ((__half2*)&pk)[3] = __floats2half2_rn(a[6], a[7]);
                *(uint4*)&As[i][hl * 8] = pk;
            }
        } else {
            #pragma unroll 1
            for (int p = 0; p < ROWS / 32; p++) {
                int i = p * 32 + rsub;
                int node = rowBase + i;
                uint4 u = make_uint4(0u, 0u, 0u, 0u);
                if (node < n)
                    u = __ldg((const uint4*)(g_xh + (size_t)node * D) + hl);
                *(uint4*)&As[i][hl * 8] = u;     // raw fp16 copy
            }
        }
        __syncthreads();

        // ---- MMA over this K=128 slab: 8 ksteps of 16, 16 rows x 64 cols/warp ----
        #pragma unroll
        for (int kk = 0; kk < 8; kk++) {
            int kb = kk * 16;
            unsigned a0 = *(unsigned*)&As[rowStrip + gpr    ][kb + tg * 2];
            unsigned a1 = *(unsigned*)&As[rowStrip + gpr + 8][kb + tg * 2];
            unsigned a2 = *(unsigned*)&As[rowStrip + gpr    ][kb + tg * 2 + 8];
            unsigned a3 = *(unsigned*)&As[rowStrip + gpr + 8][kb + tg * 2 + 8];
            #pragma unroll
            for (int t = 0; t < 8; t++) {
                unsigned b0 = *(unsigned*)&Bs[colBase + t * 8 + gpr][kb + tg * 2];
                unsigned b1 = *(unsigned*)&Bs[colBase + t * 8 + gpr][kb + tg * 2 + 8];
                mma_f16(acc[t], a0, a1, a2, a3, b0, b1);
            }
        }
    }

    // ---- epilogue: + bias, store fp32 ----
    #pragma unroll
    for (int t = 0; t < 8; t++) {
        int col = colBase + t * 8 + tg * 2;
        float bv0 = bias[col], bv1 = bias[col + 1];
        int row0 = rowBase + rowStrip + gpr;
        int row1 = row0 + 8;
        if (row0 < n) {
            float2 v = make_float2(acc[t][0] + bv0, acc[t][1] + bv1);
            *(float2*)(out + (size_t)row0 * D + col) = v;
        }
        if (row1 < n) {
            float2 v = make_float2(acc[t][2] + bv0, acc[t][3] + bv1);
            *(float2*)(out + (size_t)row1 * D + col) = v;
        }
    }
}

extern "C" void kernel_launch(void* const* d_in, const int* in_sizes, int n_in,
                              void* d_out, int out_size) {
    const float* x    = (const float*)d_in[0];
    const int*   ei_w = (const int*)d_in[1];
    const int*   et_w = (const int*)d_in[2];
    const float* W    = (const float*)d_in[3];
    const float* root = (const float*)d_in[4];
    const float* bias = (const float*)d_in[5];
    float*       out  = (float*)d_out;

    int E = in_sizes[1] / 2;
    int n = in_sizes[0] / D;
    int nb = (NSEG + 1023) / 1024;

    k_prep   <<<3200, 512>>>(W, root, x, n, ei_w, et_w);
    k_hist   <<<(E + 255) / 256, 256>>>(ei_w, et_w, E);
    k_scan1  <<<nb, 1024>>>(NSEG);
    k_scan2  <<<1, 512>>>(nb);
    k_scan3  <<<(NSEG + 255) / 256, 256>>>(NSEG, E);
    k_scatter<<<(E + 255) / 256, 256>>>(ei_w, et_w, E);
    k_fused  <<<(n + ROWS - 1) / ROWS, NTHR>>>(bias, out, n);
}